// round 4
// baseline (speedup 1.0000x reference)
#include <cuda_runtime.h>
#include <math.h>

// Problem constants
#define Dd   128
#define Kk   1024
#define Nn   4096
#define Bb   8
#define NIN  256

// Tiling
#define NT   64     // n-tile per CTA
#define KC   64     // k chunk
#define ZSS  132    // ze_s row stride (floats)
#define ESS  132    // emb_s row stride (floats)

#define NUM_OFF   (Bb * Dd * Nn)            // numer starts here
#define DEN_OFF   (Bb * Dd * Nn + Kk * Dd)  // denom starts here

// Packed f32x2 helpers (sm_103a FFMA2 path)
#define FMAF2(acc, a, b) \
    asm("fma.rn.f32x2 %0, %1, %2, %0;" : "+l"(acc) : "l"(a), "l"(b))
#define PACKF2(o, lo, hi) \
    asm("mov.b64 %0, {%1, %2};" : "=l"(o) : "r"(__float_as_uint(lo)), "r"(__float_as_uint(hi)))

__device__ __forceinline__ float unpack_sum(unsigned long long v) {
    unsigned int lo, hi;
    asm("mov.b64 {%0, %1}, %2;" : "=r"(lo), "=r"(hi) : "l"(v));
    return __uint_as_float(lo) + __uint_as_float(hi);
}

// Scratch (device globals; no allocation allowed)
__device__ float g_zsum[Kk * Dd];
__device__ float g_nsum[Kk];
__device__ float g_qsq[Kk];
__device__ float g_qsrt[Kk];

// ---------------------------------------------------------------------------
// Init: zero EMA scratch, compute per-code ||q||^2 and ||q||
// ---------------------------------------------------------------------------
__global__ void vq_init_kernel(const float* __restrict__ emb) {
    int k = blockIdx.x;      // 0..1023
    int d = threadIdx.x;     // 0..127
    float e = emb[k * Dd + d];
    g_zsum[k * Dd + d] = 0.f;
    float v = e * e;
    #pragma unroll
    for (int o = 16; o > 0; o >>= 1) v += __shfl_xor_sync(0xffffffffu, v, o);
    __shared__ float sred[4];
    if ((d & 31) == 0) sred[d >> 5] = v;
    __syncthreads();
    if (d == 0) {
        float q = sred[0] + sred[1] + sred[2] + sred[3];
        g_qsq[k] = q;
        g_qsrt[k] = sqrtf(q);
        g_nsum[k] = 0.f;
    }
}

// ---------------------------------------------------------------------------
// Fused main kernel: ze GEMM -> distance GEMM + argmin -> gather + EMA scatter
// ---------------------------------------------------------------------------
extern __shared__ float smem_f[];

__global__ void __launch_bounds__(256, 2)
vq_main_kernel(const float* __restrict__ z, const float* __restrict__ W,
               const float* __restrict__ emb, float* __restrict__ out)
{
    float* ze_s  = smem_f;
    float* U     = smem_f + NT * ZSS;
    float* Wc    = U;                    // 128*36 = 4608 floats
    float* zc    = U + 128 * 36;         // 32*68  = 2176 floats
    float* emb_s = U;                    // 64*132 = 8448 floats
    float* red_d2 = U;                   // 16*64
    float* red_dn = U + 1024;            // 16*64
    int*   red_id = (int*)(U + 2048);    // 16*64
    float* ze_sq = smem_f + 2 * NT * ZSS;        // 64
    float* s_srt = ze_sq + NT;                   // 64
    int*   ind_s = (int*)(s_srt + NT);           // 64

    const int tid = threadIdx.x;
    const int b   = blockIdx.y;
    const int n0  = blockIdx.x * NT;
    const float* zb = z + (size_t)b * NIN * Nn;

    // ================= Phase A: ze tile (128 d x 64 n), f32x2-packed over c ==
    {
        const int tdA = tid >> 4;     // 0..15 -> 8 d rows
        const int tnA = tid & 15;     // 0..15 -> 4 n cols
        const int dA = tdA * 8;
        const int nA = tnA * 4;
        unsigned long long acc2[8][4];   // packed partial sums over (even c, odd c)
        #pragma unroll
        for (int i = 0; i < 8; i++)
            #pragma unroll
            for (int j = 0; j < 4; j++) acc2[i][j] = 0ull;

        for (int c0 = 0; c0 < NIN; c0 += 32) {
            // stage W chunk [128][32]
            {
                int c4 = (tid & 7) * 4;
                int dr = tid >> 3; // 0..31
                #pragma unroll
                for (int r = 0; r < 4; r++) {
                    int d = dr + 32 * r;
                    float4 w = *(const float4*)&W[(size_t)d * NIN + c0 + c4];
                    *(float4*)&Wc[d * 36 + c4] = w;
                }
            }
            // stage z chunk [32][64]
            {
                int q4 = (tid & 15) * 4;
                int ccr = tid >> 4; // 0..15
                #pragma unroll
                for (int r = 0; r < 2; r++) {
                    int cc = ccr + 16 * r;
                    float4 v = *(const float4*)&zb[(size_t)(c0 + cc) * Nn + n0 + q4];
                    *(float4*)&zc[cc * 68 + q4] = v;
                }
            }
            __syncthreads();
            #pragma unroll 2
            for (int cc = 0; cc < 32; cc += 4) {
                float4 z0 = *(const float4*)&zc[(cc + 0) * 68 + nA];
                float4 z1 = *(const float4*)&zc[(cc + 1) * 68 + nA];
                float4 z2 = *(const float4*)&zc[(cc + 2) * 68 + nA];
                float4 z3 = *(const float4*)&zc[(cc + 3) * 68 + nA];
                // pack z pairs over c: (z0,z1) and (z2,z3) per n component
                unsigned long long p01[4], p23[4];
                PACKF2(p01[0], z0.x, z1.x); PACKF2(p01[1], z0.y, z1.y);
                PACKF2(p01[2], z0.z, z1.z); PACKF2(p01[3], z0.w, z1.w);
                PACKF2(p23[0], z2.x, z3.x); PACKF2(p23[1], z2.y, z3.y);
                PACKF2(p23[2], z2.z, z3.z); PACKF2(p23[3], z2.w, z3.w);
                #pragma unroll
                for (int i = 0; i < 8; i++) {
                    ulonglong2 wp = *(const ulonglong2*)&Wc[(dA + i) * 36 + cc];
                    #pragma unroll
                    for (int j = 0; j < 4; j++) {
                        FMAF2(acc2[i][j], wp.x, p01[j]);
                        FMAF2(acc2[i][j], wp.y, p23[j]);
                    }
                }
            }
            __syncthreads();
        }
        // write transposed ze_s[n][d]
        #pragma unroll
        for (int j = 0; j < 4; j++) {
            int n = nA + j;
            float4 v0 = make_float4(unpack_sum(acc2[0][j]), unpack_sum(acc2[1][j]),
                                    unpack_sum(acc2[2][j]), unpack_sum(acc2[3][j]));
            float4 v1 = make_float4(unpack_sum(acc2[4][j]), unpack_sum(acc2[5][j]),
                                    unpack_sum(acc2[6][j]), unpack_sum(acc2[7][j]));
            *(float4*)&ze_s[n * ZSS + dA]     = v0;
            *(float4*)&ze_s[n * ZSS + dA + 4] = v1;
        }
    }
    __syncthreads();

    // per-n ||ze||^2 and ||ze||
    if (tid < NT) {
        const float* row = &ze_s[tid * ZSS];
        float s = 0.f;
        #pragma unroll 8
        for (int d = 0; d < Dd; d += 4) {
            float4 v = *(const float4*)&row[d];
            s += v.x * v.x + v.y * v.y + v.z * v.z + v.w * v.w;
        }
        ze_sq[tid] = s;
        s_srt[tid] = sqrtf(s);
    }
    __syncthreads();

    // ================= Phase B: distances + running argmin (f32x2) =========
    const int tk = tid >> 4;  // 0..15 -> 4 k rows
    const int tn = tid & 15;  // n's = tn + 16*j
    float bd2[4], bdn[4];
    int   bid_[4];
    float zsq_r[4], ssr_r[4];
    #pragma unroll
    for (int j = 0; j < 4; j++) {
        bd2[j] = __int_as_float(0x7f800000);  // +inf
        bdn[j] = 1.f;
        bid_[j] = 0;
        zsq_r[j] = ze_sq[tn + 16 * j];
        ssr_r[j] = s_srt[tn + 16 * j];
    }

    for (int kc = 0; kc < Kk; kc += KC) {
        // stage emb chunk [64][128]
        {
            int row = tid >> 5;        // 0..7
            int c4 = (tid & 31) * 4;   // 0..124
            #pragma unroll
            for (int r = 0; r < 8; r++) {
                int kk = row + 8 * r;
                float4 v = *(const float4*)&emb[(size_t)(kc + kk) * Dd + c4];
                *(float4*)&emb_s[kk * ESS + c4] = v;
            }
        }
        __syncthreads();

        unsigned long long acc2[4][4];
        #pragma unroll
        for (int i = 0; i < 4; i++)
            #pragma unroll
            for (int j = 0; j < 4; j++) acc2[i][j] = 0ull;

        #pragma unroll 4
        for (int d = 0; d < Dd; d += 4) {
            ulonglong2 a2[4], q2[4];
            #pragma unroll
            for (int i = 0; i < 4; i++)
                a2[i] = *(const ulonglong2*)&emb_s[(tk * 4 + i) * ESS + d];
            #pragma unroll
            for (int j = 0; j < 4; j++)
                q2[j] = *(const ulonglong2*)&ze_s[(tn + 16 * j) * ZSS + d];
            #pragma unroll
            for (int i = 0; i < 4; i++)
                #pragma unroll
                for (int j = 0; j < 4; j++) {
                    FMAF2(acc2[i][j], a2[i].x, q2[j].x);
                    FMAF2(acc2[i][j], a2[i].y, q2[j].y);
                }
        }

        // epilogue: scaled-distance compare via cross-multiplication
        #pragma unroll
        for (int i = 0; i < 4; i++) {
            int k = kc + tk * 4 + i;
            float qsq = g_qsq[k];
            float qsr = g_qsrt[k];
            #pragma unroll
            for (int j = 0; j < 4; j++) {
                float dotv = unpack_sum(acc2[i][j]);
                float d2 = fmaf(-2.f, dotv, zsq_r[j] + qsq);
                d2 = fmaxf(d2, 0.f);
                float den = ssr_r[j] + qsr;
                float dn2 = den * den;
                float lhs = d2 * bdn[j];
                float rhs = bd2[j] * dn2;
                if (lhs < rhs || (lhs == rhs && k < bid_[j])) {
                    bd2[j] = d2; bdn[j] = dn2; bid_[j] = k;
                }
            }
        }
        __syncthreads();  // done with emb_s before next stage
    }

    // cross-thread argmin reduce (16 tk groups per n)
    #pragma unroll
    for (int j = 0; j < 4; j++) {
        int n = tn + 16 * j;
        red_d2[tk * NT + n] = bd2[j];
        red_dn[tk * NT + n] = bdn[j];
        red_id[tk * NT + n] = bid_[j];
    }
    __syncthreads();
    if (tid < NT) {
        int n = tid;
        float cd2 = red_d2[n], cdn = red_dn[n];
        int ci = red_id[n];
        #pragma unroll
        for (int t = 1; t < 16; t++) {
            float d2 = red_d2[t * NT + n];
            float dn = red_dn[t * NT + n];
            int   ii = red_id[t * NT + n];
            float lhs = d2 * cdn, rhs = cd2 * dn;
            if (lhs < rhs || (lhs == rhs && ii < ci)) { cd2 = d2; cdn = dn; ci = ii; }
        }
        ind_s[n] = ci;
        atomicAdd(&g_nsum[ci], 1.0f);
    }
    __syncthreads();

    // ================= Epilogue: gather zq + EMA scatter =================
    {
        int nn = tid & 63;
        int dblk = tid >> 6;  // 0..3
        int ci = ind_s[nn];
        const float* erow = emb + (size_t)ci * Dd;
        float* zsr = g_zsum + (size_t)ci * Dd;
        float* oz = out + (size_t)b * Dd * Nn + (size_t)(n0 + nn);
        const float* zrow = &ze_s[nn * ZSS];
        #pragma unroll 4
        for (int dd = 0; dd < 32; dd++) {
            int d = dblk * 32 + dd;
            oz[(size_t)d * Nn] = erow[d];
            atomicAdd(&zsr[d], zrow[d]);
        }
    }
}

// ---------------------------------------------------------------------------
// Finalize EMA outputs
// ---------------------------------------------------------------------------
__global__ void vq_ema_kernel(const float* __restrict__ numer,
                              const float* __restrict__ denom,
                              float* __restrict__ out)
{
    int i = blockIdx.x * blockDim.x + threadIdx.x;  // 0..131071
    out[NUM_OFF + i] = 0.99f * numer[i] + 0.01f * g_zsum[i];
    if (i < Kk)
        out[DEN_OFF + i] = 0.99f * denom[i] + 0.01f * g_nsum[i];
}

// ---------------------------------------------------------------------------
extern "C" void kernel_launch(void* const* d_in, const int* in_sizes, int n_in,
                              void* d_out, int out_size)
{
    const float* z     = (const float*)d_in[0];
    const float* W     = (const float*)d_in[1];
    const float* emb   = (const float*)d_in[2];
    const float* numer = (const float*)d_in[3];
    const float* denom = (const float*)d_in[4];
    float* out = (float*)d_out;

    const int smem_bytes = (2 * NT * ZSS + 2 * NT) * 4 + NT * 4;  // 68352
    cudaFuncSetAttribute(vq_main_kernel,
                         cudaFuncAttributeMaxDynamicSharedMemorySize, smem_bytes);

    vq_init_kernel<<<Kk, Dd>>>(emb);
    dim3 grid(Nn / NT, Bb);
    vq_main_kernel<<<grid, 256, smem_bytes>>>(z, W, emb, out);
    vq_ema_kernel<<<(Kk * Dd) / 256, 256>>>(numer, denom, out);
}

// round 9
// speedup vs baseline: 1.4932x; 1.4932x over previous
#include <cuda_runtime.h>
#include <cuda_bf16.h>
#include <math.h>
#include <stdint.h>

// Problem constants
#define Dd   128
#define Kk   1024
#define Nn   4096
#define Bb   8
#define NIN  256
#define TOK  (Bb * Nn)        // 32768 tokens
#define TPC  128              // tokens per CTA in dist kernel
#define KCH  64               // codes per streamed chunk
#define NCH  (Kk / KCH)       // 16 chunks

#define NUM_OFF (Bb * Dd * Nn)
#define DEN_OFF (Bb * Dd * Nn + Kk * Dd)

// K2 tiling (scalar ze GEMM, proven R1 phase A)
#define NT  64
#define ZSS 132

// dist kernel smem geometry (bytes)
#define ARS_B  272                      // padded row stride (136 bf16) -> 16B aligned, conflict-free
#define AB     (128 * ARS_B)            // 34816 per A split
#define BB     (KCH * ARS_B)            // 17408 per B split
#define OFF_A    0                      // 3 * AB = 104448
#define OFF_B    104448                 // 2 bufs * 3 * BB = 104448
#define OFF_QSQ  208896                 // 4096
#define OFF_QSRT 212992                 // 4096
#define OFF_CNT  217088                 // 4096
#define OFF_IND  221184                 // 512
#define SM_TOTAL 221696

// ---------------------------------------------------------------------------
// Device global scratch (no allocations allowed)
// ---------------------------------------------------------------------------
__device__ __align__(256) __nv_bfloat16 g_a0[TOK * Dd];
__device__ __align__(256) __nv_bfloat16 g_a1[TOK * Dd];
__device__ __align__(256) __nv_bfloat16 g_a2[TOK * Dd];
__device__ __align__(256) __nv_bfloat16 g_e0[Kk * Dd];
__device__ __align__(256) __nv_bfloat16 g_e1[Kk * Dd];
__device__ __align__(256) __nv_bfloat16 g_e2[Kk * Dd];
__device__ float g_zsq[TOK];
__device__ float g_zsrt[TOK];
__device__ float g_qsq[Kk];
__device__ float g_qsrt[Kk];
__device__ float g_zsum[Kk * Dd];
__device__ float g_nsum[Kk];

// ---------------------------------------------------------------------------
// PTX helpers (all baseline sm_80+ features; NO sm_103a-only instructions)
// ---------------------------------------------------------------------------
__device__ __forceinline__ uint32_t smem_u32(const void* p) {
    uint32_t a;
    asm("{ .reg .u64 t; cvta.to.shared.u64 t, %1; cvt.u32.u64 %0, t; }" : "=r"(a) : "l"(p));
    return a;
}
#define CP16(dst, src) \
    asm volatile("cp.async.cg.shared.global [%0], [%1], 16;" :: "r"(dst), "l"(src))
#define CP_COMMIT() asm volatile("cp.async.commit_group;" ::: "memory")
#define CP_WAIT0()  asm volatile("cp.async.wait_group 0;" ::: "memory")
#define CP_WAIT1()  asm volatile("cp.async.wait_group 1;" ::: "memory")

__device__ __forceinline__ void ldsm_x4(uint32_t* r, uint32_t addr) {
    asm volatile("ldmatrix.sync.aligned.m8n8.x4.shared.b16 {%0,%1,%2,%3}, [%4];"
        : "=r"(r[0]), "=r"(r[1]), "=r"(r[2]), "=r"(r[3]) : "r"(addr));
}
__device__ __forceinline__ void ldsm_x2(uint32_t* r, uint32_t addr) {
    asm volatile("ldmatrix.sync.aligned.m8n8.x2.shared.b16 {%0,%1}, [%2];"
        : "=r"(r[0]), "=r"(r[1]) : "r"(addr));
}
__device__ __forceinline__ void mma_bf16(float* d, const uint32_t* a, const uint32_t* b) {
    asm volatile("mma.sync.aligned.m16n8k16.row.col.f32.bf16.bf16.f32 "
        "{%0,%1,%2,%3}, {%4,%5,%6,%7}, {%8,%9}, {%0,%1,%2,%3};"
        : "+f"(d[0]), "+f"(d[1]), "+f"(d[2]), "+f"(d[3])
        : "r"(a[0]), "r"(a[1]), "r"(a[2]), "r"(a[3]), "r"(b[0]), "r"(b[1]));
}

// ---------------------------------------------------------------------------
// K1: emb bf16x3 splits + ||q|| stats + zero EMA scratch
// ---------------------------------------------------------------------------
__global__ void vq_prep_kernel(const float* __restrict__ emb) {
    int k = blockIdx.x, d = threadIdx.x;
    float e = emb[k * Dd + d];
    __nv_bfloat16 b0 = __float2bfloat16_rn(e);
    float r1 = e - __bfloat162float(b0);
    __nv_bfloat16 b1 = __float2bfloat16_rn(r1);
    float r2 = r1 - __bfloat162float(b1);
    __nv_bfloat16 b2 = __float2bfloat16_rn(r2);
    g_e0[k * Dd + d] = b0;
    g_e1[k * Dd + d] = b1;
    g_e2[k * Dd + d] = b2;
    g_zsum[k * Dd + d] = 0.f;
    float v = e * e;
    #pragma unroll
    for (int o = 16; o > 0; o >>= 1) v += __shfl_xor_sync(0xffffffffu, v, o);
    __shared__ float sred[4];
    if ((d & 31) == 0) sred[d >> 5] = v;
    __syncthreads();
    if (d == 0) {
        float q = sred[0] + sred[1] + sred[2] + sred[3];
        g_qsq[k] = q;
        g_qsrt[k] = sqrtf(q);
        g_nsum[k] = 0.f;
    }
}

// ---------------------------------------------------------------------------
// K2: scalar fp32 ze GEMM -> bf16x3 splits + ||ze|| stats (proven structure)
// ---------------------------------------------------------------------------
extern __shared__ float smem_f[];

__global__ void __launch_bounds__(256)
vq_ze_kernel(const float* __restrict__ z, const float* __restrict__ W)
{
    float* ze_s = smem_f;                 // [64][132]
    float* Wc   = smem_f + NT * ZSS;      // 128*36
    float* zc   = Wc + 128 * 36;          // 32*68

    const int tid = threadIdx.x;
    const int b   = blockIdx.y;
    const int n0  = blockIdx.x * NT;
    const int T0  = b * Nn + n0;
    const float* zb = z + (size_t)b * NIN * Nn;

    const int tdA = tid >> 4;
    const int tnA = tid & 15;
    const int dA = tdA * 8;
    const int nA = tnA * 4;
    float acc[8][4];
    #pragma unroll
    for (int i = 0; i < 8; i++)
        #pragma unroll
        for (int j = 0; j < 4; j++) acc[i][j] = 0.f;

    for (int c0 = 0; c0 < NIN; c0 += 32) {
        {
            int c4 = (tid & 7) * 4;
            int dr = tid >> 3;
            #pragma unroll
            for (int r = 0; r < 4; r++) {
                int d = dr + 32 * r;
                float4 w = *(const float4*)&W[(size_t)d * NIN + c0 + c4];
                *(float4*)&Wc[d * 36 + c4] = w;
            }
        }
        {
            int q4 = (tid & 15) * 4;
            int ccr = tid >> 4;
            #pragma unroll
            for (int r = 0; r < 2; r++) {
                int cc = ccr + 16 * r;
                float4 v = *(const float4*)&zb[(size_t)(c0 + cc) * Nn + n0 + q4];
                *(float4*)&zc[cc * 68 + q4] = v;
            }
        }
        __syncthreads();
        #pragma unroll 2
        for (int cc = 0; cc < 32; cc += 4) {
            float4 w4[8], z4[4];
            #pragma unroll
            for (int i = 0; i < 8; i++) w4[i] = *(const float4*)&Wc[(dA + i) * 36 + cc];
            #pragma unroll
            for (int u = 0; u < 4; u++) z4[u] = *(const float4*)&zc[(cc + u) * 68 + nA];
            #pragma unroll
            for (int i = 0; i < 8; i++) {
                float4 w = w4[i];
                acc[i][0] = fmaf(w.x, z4[0].x, fmaf(w.y, z4[1].x, fmaf(w.z, z4[2].x, fmaf(w.w, z4[3].x, acc[i][0]))));
                acc[i][1] = fmaf(w.x, z4[0].y, fmaf(w.y, z4[1].y, fmaf(w.z, z4[2].y, fmaf(w.w, z4[3].y, acc[i][1]))));
                acc[i][2] = fmaf(w.x, z4[0].z, fmaf(w.y, z4[1].z, fmaf(w.z, z4[2].z, fmaf(w.w, z4[3].z, acc[i][2]))));
                acc[i][3] = fmaf(w.x, z4[0].w, fmaf(w.y, z4[1].w, fmaf(w.z, z4[2].w, fmaf(w.w, z4[3].w, acc[i][3]))));
            }
        }
        __syncthreads();
    }
    #pragma unroll
    for (int j = 0; j < 4; j++) {
        int n = nA + j;
        float4 v0 = make_float4(acc[0][j], acc[1][j], acc[2][j], acc[3][j]);
        float4 v1 = make_float4(acc[4][j], acc[5][j], acc[6][j], acc[7][j]);
        *(float4*)&ze_s[n * ZSS + dA]     = v0;
        *(float4*)&ze_s[n * ZSS + dA + 4] = v1;
    }
    __syncthreads();

    if (tid < NT) {
        const float* row = &ze_s[tid * ZSS];
        float s = 0.f;
        #pragma unroll 8
        for (int d = 0; d < Dd; d += 4) {
            float4 v = *(const float4*)&row[d];
            s += v.x * v.x + v.y * v.y + v.z * v.z + v.w * v.w;
        }
        g_zsq[T0 + tid]  = s;
        g_zsrt[T0 + tid] = sqrtf(s);
    }

    for (int i = tid; i < NT * Dd; i += 256) {
        int tl = i >> 7;
        int d  = i & 127;
        float e = ze_s[tl * ZSS + d];
        __nv_bfloat16 b0 = __float2bfloat16_rn(e);
        float r1 = e - __bfloat162float(b0);
        __nv_bfloat16 b1 = __float2bfloat16_rn(r1);
        float r2 = r1 - __bfloat162float(b1);
        __nv_bfloat16 b2 = __float2bfloat16_rn(r2);
        size_t gi = (size_t)(T0 + tl) * Dd + d;
        g_a0[gi] = b0; g_a1[gi] = b1; g_a2[gi] = b2;
    }
}

// ---------------------------------------------------------------------------
// K3: mma.sync bf16x3 distance GEMM + argmin + gather + EMA scatter
// ---------------------------------------------------------------------------
__device__ __forceinline__ void stage_B_chunk(uint32_t sb, int buf, int chunk, int tid) {
    const __nv_bfloat16* srcs[3] = {
        g_e0 + (size_t)chunk * KCH * Dd,
        g_e1 + (size_t)chunk * KCH * Dd,
        g_e2 + (size_t)chunk * KCH * Dd };
    uint32_t base = sb + OFF_B + buf * (3 * BB);
    #pragma unroll
    for (int s = 0; s < 3; s++) {
        const char* src = (const char*)srcs[s];
        // 64 rows x 256B -> stride 272B; 1024 16B transfers / 256 threads
        #pragma unroll
        for (int i = tid; i < 1024; i += 256) {
            int r = i >> 4, c = i & 15;
            CP16(base + s * BB + r * ARS_B + c * 16, src + r * 256 + c * 16);
        }
    }
}

__global__ void __launch_bounds__(256, 1)
vq_dist_kernel(const float* __restrict__ emb, float* __restrict__ out)
{
    extern __shared__ char smem_c[];
    const uint32_t sb = smem_u32(smem_c);
    const int tid  = threadIdx.x;
    const int lane = tid & 31;
    const int w    = tid >> 5;           // 8 warps
    const int wt0  = w * 16;             // warp token base (CTA-local)
    const int T0   = blockIdx.x * TPC;

    float* s_qsq  = (float*)(smem_c + OFF_QSQ);
    float* s_qsrt = (float*)(smem_c + OFF_QSRT);
    int*   s_cnt  = (int*)(smem_c + OFF_CNT);
    int*   s_ind  = (int*)(smem_c + OFF_IND);

    for (int i = tid; i < Kk; i += 256) s_cnt[i] = 0;

    // ---- stage A (token splits) + all code norms : group G0 ----
    {
        const __nv_bfloat16* srcs[3] = {
            g_a0 + (size_t)T0 * Dd, g_a1 + (size_t)T0 * Dd, g_a2 + (size_t)T0 * Dd };
        #pragma unroll
        for (int s = 0; s < 3; s++) {
            const char* src = (const char*)srcs[s];
            #pragma unroll
            for (int i = tid; i < 2048; i += 256) {
                int r = i >> 4, c = i & 15;
                CP16(sb + OFF_A + s * AB + r * ARS_B + c * 16, src + r * 256 + c * 16);
            }
        }
        CP16(sb + OFF_QSQ  + tid * 16, (const char*)g_qsq  + tid * 16);
        CP16(sb + OFF_QSRT + tid * 16, (const char*)g_qsrt + tid * 16);
        CP_COMMIT();
    }
    // prefetch B chunk 0 : group G1
    stage_B_chunk(sb, 0, 0, tid);
    CP_COMMIT();

    // per-thread token norms (slot0 = wt0 + lane/4, slot1 = +8)
    const float zsq0 = g_zsq[T0 + wt0 + (lane >> 2)];
    const float zsr0 = g_zsrt[T0 + wt0 + (lane >> 2)];
    const float zsq1 = g_zsq[T0 + wt0 + (lane >> 2) + 8];
    const float zsr1 = g_zsrt[T0 + wt0 + (lane >> 2) + 8];

    // ldmatrix base addresses
    uint32_t a_addr[3];
    {
        uint32_t arow = wt0 + (lane & 15);
        uint32_t acol = ((lane >> 4) << 3);   // 0 or 8 (bf16 elements)
        #pragma unroll
        for (int s = 0; s < 3; s++)
            a_addr[s] = sb + OFF_A + s * AB + arow * ARS_B + acol * 2;
    }
    const uint32_t b_lane_off = (uint32_t)((lane & 7) * ARS_B + (((lane >> 3) & 1) << 4));
    const uint32_t b_base0 = sb + OFF_B + b_lane_off;

    // running argmin state (cross-multiplied scaled distance)
    float bd2_0 = __int_as_float(0x7f800000), bdn_0 = 1.f;
    float bd2_1 = __int_as_float(0x7f800000), bdn_1 = 1.f;
    int   bid_0 = 0, bid_1 = 0;

    for (int cc = 0; cc < NCH; cc++) {
        if (cc + 1 < NCH) {
            stage_B_chunk(sb, (cc + 1) & 1, cc + 1, tid);
            CP_COMMIT();
            CP_WAIT1();
        } else {
            CP_WAIT0();
        }
        __syncthreads();   // chunk cc (and A/norms at cc=0) fully staged

        float acc[8][4];
        #pragma unroll
        for (int nt = 0; nt < 8; nt++)
            #pragma unroll
            for (int q = 0; q < 4; q++) acc[nt][q] = 0.f;

        const uint32_t bbuf = b_base0 + (uint32_t)((cc & 1) * (3 * BB));

        #pragma unroll 2
        for (int ks = 0; ks < 8; ks++) {
            uint32_t a0f[4], a1f[4], a2f[4];
            ldsm_x4(a0f, a_addr[0] + ks * 32);
            ldsm_x4(a1f, a_addr[1] + ks * 32);
            ldsm_x4(a2f, a_addr[2] + ks * 32);
            #pragma unroll
            for (int nt = 0; nt < 8; nt++) {
                uint32_t b0f[2], b1f[2], b2f[2];
                uint32_t bt = bbuf + (uint32_t)(nt * 8 * ARS_B + ks * 32);
                ldsm_x2(b0f, bt);
                ldsm_x2(b1f, bt + BB);
                ldsm_x2(b2f, bt + 2 * BB);
                mma_bf16(acc[nt], a0f, b0f);
                mma_bf16(acc[nt], a1f, b0f);
                mma_bf16(acc[nt], a0f, b1f);
                mma_bf16(acc[nt], a1f, b1f);
                mma_bf16(acc[nt], a2f, b0f);
                mma_bf16(acc[nt], a0f, b2f);
            }
        }

        // fold chunk dots into running argmin
        #pragma unroll
        for (int nt = 0; nt < 8; nt++) {
            int cb = cc * KCH + nt * 8 + ((lane & 3) << 1);
            #pragma unroll
            for (int ci = 0; ci < 2; ci++) {
                int k = cb + ci;
                float qs = s_qsq[k];
                float qr = s_qsrt[k];
                {
                    float d2 = fmaxf(fmaf(-2.f, acc[nt][ci], zsq0 + qs), 0.f);
                    float den = zsr0 + qr, dn2 = den * den;
                    float lhs = d2 * bdn_0, rhs = bd2_0 * dn2;
                    if (lhs < rhs) { bd2_0 = d2; bdn_0 = dn2; bid_0 = k; }
                }
                {
                    float d2 = fmaxf(fmaf(-2.f, acc[nt][2 + ci], zsq1 + qs), 0.f);
                    float den = zsr1 + qr, dn2 = den * den;
                    float lhs = d2 * bdn_1, rhs = bd2_1 * dn2;
                    if (lhs < rhs) { bd2_1 = d2; bdn_1 = dn2; bid_1 = k; }
                }
            }
        }
        __syncthreads();   // readers done before next prefetch overwrites other buf
    }

    // reduce across the 4 lanes of each token quad (lanes differ only in code set)
    #pragma unroll
    for (int off = 1; off < 4; off <<= 1) {
        float od2 = __shfl_xor_sync(0xffffffffu, bd2_0, off);
        float odn = __shfl_xor_sync(0xffffffffu, bdn_0, off);
        int   oid = __shfl_xor_sync(0xffffffffu, bid_0, off);
        float lhs = od2 * bdn_0, rhs = bd2_0 * odn;
        if (lhs < rhs || (lhs == rhs && oid < bid_0)) { bd2_0 = od2; bdn_0 = odn; bid_0 = oid; }
        od2 = __shfl_xor_sync(0xffffffffu, bd2_1, off);
        odn = __shfl_xor_sync(0xffffffffu, bdn_1, off);
        oid = __shfl_xor_sync(0xffffffffu, bid_1, off);
        lhs = od2 * bdn_1; rhs = bd2_1 * odn;
        if (lhs < rhs || (lhs == rhs && oid < bid_1)) { bd2_1 = od2; bdn_1 = odn; bid_1 = oid; }
    }
    if ((lane & 3) == 0) {
        s_ind[wt0 + (lane >> 2)]     = bid_0;
        s_ind[wt0 + (lane >> 2) + 8] = bid_1;
    }
    __syncthreads();

    // ---- counts ----
    if (tid < TPC) atomicAdd(&s_cnt[s_ind[tid]], 1);

    // ---- zq gather + EMA scatter : 2 threads per token ----
    {
        int tl   = tid >> 1;
        int half = tid & 1;
        int ci   = s_ind[tl];
        int token = T0 + tl;
        int b = token >> 12;
        int n = token & (Nn - 1);
        const float4* er = (const float4*)(emb + (size_t)ci * Dd + half * 64);
        float* op = out + (size_t)b * Dd * Nn + n + (size_t)(half * 64) * Nn;
        #pragma unroll 4
        for (int d4 = 0; d4 < 16; d4++) {
            float4 v = er[d4];
            op[(size_t)(d4 * 4 + 0) * Nn] = v.x;
            op[(size_t)(d4 * 4 + 1) * Nn] = v.y;
            op[(size_t)(d4 * 4 + 2) * Nn] = v.z;
            op[(size_t)(d4 * 4 + 3) * Nn] = v.w;
        }
        // scatter: reconstruct ze from the 3 A splits in smem
        float* zs = g_zsum + (size_t)ci * Dd + half * 64;
        uint32_t arow = sb + OFF_A + (uint32_t)(tl * ARS_B + half * 128);
        #pragma unroll 2
        for (int c8 = 0; c8 < 8; c8++) {
            uint4 v0 = *(const uint4*)(smem_c + (arow - sb) + c8 * 16);
            uint4 v1 = *(const uint4*)(smem_c + (arow - sb) + AB + c8 * 16);
            uint4 v2 = *(const uint4*)(smem_c + (arow - sb) + 2 * AB + c8 * 16);
            const __nv_bfloat16* p0 = (const __nv_bfloat16*)&v0;
            const __nv_bfloat16* p1 = (const __nv_bfloat16*)&v1;
            const __nv_bfloat16* p2 = (const __nv_bfloat16*)&v2;
            #pragma unroll
            for (int e = 0; e < 8; e++) {
                float ze = __bfloat162float(p0[e]) + __bfloat162float(p1[e]) + __bfloat162float(p2[e]);
                atomicAdd(&zs[c8 * 8 + e], ze);
            }
        }
    }
    __syncthreads();
    for (int i = tid; i < Kk; i += 256) {
        int c = s_cnt[i];
        if (c) atomicAdd(&g_nsum[i], (float)c);
    }
}

// ---------------------------------------------------------------------------
// K4: finalize EMA outputs
// ---------------------------------------------------------------------------
__global__ void vq_ema_kernel(const float* __restrict__ numer,
                              const float* __restrict__ denom,
                              float* __restrict__ out)
{
    int i = blockIdx.x * blockDim.x + threadIdx.x;
    out[NUM_OFF + i] = 0.99f * numer[i] + 0.01f * g_zsum[i];
    if (i < Kk)
        out[DEN_OFF + i] = 0.99f * denom[i] + 0.01f * g_nsum[i];
}

// ---------------------------------------------------------------------------
extern "C" void kernel_launch(void* const* d_in, const int* in_sizes, int n_in,
                              void* d_out, int out_size)
{
    const float* z     = (const float*)d_in[0];
    const float* W     = (const float*)d_in[1];
    const float* emb   = (const float*)d_in[2];
    const float* numer = (const float*)d_in[3];
    const float* denom = (const float*)d_in[4];
    float* out = (float*)d_out;

    const int ze_smem = (NT * ZSS + 128 * 36 + 32 * 68) * 4;  // 60928 B
    cudaFuncSetAttribute(vq_ze_kernel,
                         cudaFuncAttributeMaxDynamicSharedMemorySize, ze_smem);
    cudaFuncSetAttribute(vq_dist_kernel,
                         cudaFuncAttributeMaxDynamicSharedMemorySize, SM_TOTAL);

    vq_prep_kernel<<<Kk, Dd>>>(emb);
    dim3 gz(Nn / NT, Bb);
    vq_ze_kernel<<<gz, 256, ze_smem>>>(z, W);
    vq_dist_kernel<<<TOK / TPC, 256, SM_TOTAL>>>(emb, out);
    vq_ema_kernel<<<(Kk * Dd) / 256, 256>>>(numer, denom, out);
}

// round 10
// speedup vs baseline: 1.5761x; 1.0555x over previous
#include <cuda_runtime.h>
#include <cuda_bf16.h>
#include <math.h>
#include <stdint.h>

// Problem constants
#define Dd   128
#define Kk   1024
#define Nn   4096
#define Bb   8
#define NIN  256
#define TOK  (Bb * Nn)        // 32768 tokens
#define TPC  128              // tokens per CTA in dist kernel
#define KCH  64               // codes per streamed chunk
#define NCH  (Kk / KCH)       // 16 chunks

#define NUM_OFF (Bb * Dd * Nn)
#define DEN_OFF (Bb * Dd * Nn + Kk * Dd)

// K2 tiling (scalar ze GEMM, proven)
#define NT  64
#define ZSS 132

// padded split layout: 136 bf16 per row = 272B (16B aligned, ldmatrix conflict-free)
#define PRS    136
#define ARS_B  272
#define AB     (128 * ARS_B)            // 34816 per A split
#define BB     (KCH * ARS_B)            // 17408 per B split

// dist kernel smem geometry (bytes)
#define OFF_A    0                      // 3 * AB = 104448
#define OFF_B    104448                 // 2 bufs * 3 * BB = 104448
#define OFF_QSQ  208896                 // 4096
#define OFF_QSRT 212992                 // 4096
#define OFF_CNT  217088                 // 4096
#define OFF_IND  221184                 // 512
#define OFF_MBAR 221696                 // 3 barriers x 8B
#define SM_TOTAL 221824

// ---------------------------------------------------------------------------
// Device global scratch (no allocations allowed) — padded split layouts
// ---------------------------------------------------------------------------
__device__ __align__(256) __nv_bfloat16 g_a0[TOK * PRS];
__device__ __align__(256) __nv_bfloat16 g_a1[TOK * PRS];
__device__ __align__(256) __nv_bfloat16 g_a2[TOK * PRS];
__device__ __align__(256) __nv_bfloat16 g_e0[Kk * PRS];
__device__ __align__(256) __nv_bfloat16 g_e1[Kk * PRS];
__device__ __align__(256) __nv_bfloat16 g_e2[Kk * PRS];
__device__ float g_zsq[TOK];
__device__ float g_zsrt[TOK];
__device__ float g_qsq[Kk];
__device__ float g_qsrt[Kk];
__device__ float g_zsum[Kk * Dd];
__device__ float g_nsum[Kk];

// ---------------------------------------------------------------------------
// PTX helpers (sm_80/sm_90 baseline only; nothing sm_103a-gated)
// ---------------------------------------------------------------------------
__device__ __forceinline__ uint32_t smem_u32(const void* p) {
    uint32_t a;
    asm("{ .reg .u64 t; cvta.to.shared.u64 t, %1; cvt.u32.u64 %0, t; }" : "=r"(a) : "l"(p));
    return a;
}
#define MBARRIER_INIT(mb, c) \
    asm volatile("mbarrier.init.shared.b64 [%0], %1;" :: "r"((uint32_t)(mb)), "r"((uint32_t)(c)) : "memory")
#define MBARRIER_EXPECT_TX(mb, bytes) \
    asm volatile("mbarrier.arrive.expect_tx.shared.b64 _, [%0], %1;" :: "r"((uint32_t)(mb)), "r"((uint32_t)(bytes)) : "memory")
#define FENCE_PROXY_ASYNC() asm volatile("fence.proxy.async.shared::cta;" ::: "memory")
#define MBARRIER_WAIT_PARITY(mb, ph) do { \
    uint32_t _mb = (uint32_t)(mb), _ph = (uint32_t)(ph), _done; \
    asm volatile("{ .reg .pred p; mbarrier.try_wait.parity.acquire.cta.shared::cta.b64 p, [%1], %2; selp.b32 %0, 1, 0, p; }" \
                 : "=r"(_done) : "r"(_mb), "r"(_ph) : "memory"); \
    if (!_done) { \
        asm volatile("{ .reg .pred P1; WL_%=: mbarrier.try_wait.parity.acquire.cta.shared::cta.b64 P1, [%0], %1, 0x989680; @P1 bra.uni WD_%=; bra.uni WL_%=; WD_%=: }" \
                     :: "r"(_mb), "r"(_ph) : "memory"); \
    } \
} while (0)
#define BULK_G2S(dst, src, bytes, mb) \
    asm volatile("cp.async.bulk.shared::cluster.global.mbarrier::complete_tx::bytes [%0], [%1], %2, [%3];" \
                 :: "r"((uint32_t)(dst)), "l"(src), "r"((uint32_t)(bytes)), "r"((uint32_t)(mb)) : "memory")

__device__ __forceinline__ void ldsm_x4(uint32_t* r, uint32_t addr) {
    asm volatile("ldmatrix.sync.aligned.m8n8.x4.shared.b16 {%0,%1,%2,%3}, [%4];"
        : "=r"(r[0]), "=r"(r[1]), "=r"(r[2]), "=r"(r[3]) : "r"(addr));
}
__device__ __forceinline__ void mma_bf16(float* d, const uint32_t* a, const uint32_t* b) {
    asm volatile("mma.sync.aligned.m16n8k16.row.col.f32.bf16.bf16.f32 "
        "{%0,%1,%2,%3}, {%4,%5,%6,%7}, {%8,%9}, {%0,%1,%2,%3};"
        : "+f"(d[0]), "+f"(d[1]), "+f"(d[2]), "+f"(d[3])
        : "r"(a[0]), "r"(a[1]), "r"(a[2]), "r"(a[3]), "r"(b[0]), "r"(b[1]));
}

// ---------------------------------------------------------------------------
// K1: emb bf16x3 splits (padded) + ||q|| stats + zero EMA scratch
// ---------------------------------------------------------------------------
__global__ void vq_prep_kernel(const float* __restrict__ emb) {
    int k = blockIdx.x, d = threadIdx.x;
    float e = emb[k * Dd + d];
    __nv_bfloat16 b0 = __float2bfloat16_rn(e);
    float r1 = e - __bfloat162float(b0);
    __nv_bfloat16 b1 = __float2bfloat16_rn(r1);
    float r2 = r1 - __bfloat162float(b1);
    __nv_bfloat16 b2 = __float2bfloat16_rn(r2);
    g_e0[k * PRS + d] = b0;
    g_e1[k * PRS + d] = b1;
    g_e2[k * PRS + d] = b2;
    g_zsum[k * Dd + d] = 0.f;
    float v = e * e;
    #pragma unroll
    for (int o = 16; o > 0; o >>= 1) v += __shfl_xor_sync(0xffffffffu, v, o);
    __shared__ float sred[4];
    if ((d & 31) == 0) sred[d >> 5] = v;
    __syncthreads();
    if (d == 0) {
        float q = sred[0] + sred[1] + sred[2] + sred[3];
        g_qsq[k] = q;
        g_qsrt[k] = sqrtf(q);
        g_nsum[k] = 0.f;
    }
}

// ---------------------------------------------------------------------------
// K2: scalar fp32 ze GEMM -> padded bf16x3 splits + ||ze|| stats (proven)
// ---------------------------------------------------------------------------
extern __shared__ float smem_f[];

__global__ void __launch_bounds__(256)
vq_ze_kernel(const float* __restrict__ z, const float* __restrict__ W)
{
    float* ze_s = smem_f;                 // [64][132]
    float* Wc   = smem_f + NT * ZSS;      // 128*36
    float* zc   = Wc + 128 * 36;          // 32*68

    const int tid = threadIdx.x;
    const int b   = blockIdx.y;
    const int n0  = blockIdx.x * NT;
    const int T0  = b * Nn + n0;
    const float* zb = z + (size_t)b * NIN * Nn;

    const int tdA = tid >> 4;
    const int tnA = tid & 15;
    const int dA = tdA * 8;
    const int nA = tnA * 4;
    float acc[8][4];
    #pragma unroll
    for (int i = 0; i < 8; i++)
        #pragma unroll
        for (int j = 0; j < 4; j++) acc[i][j] = 0.f;

    for (int c0 = 0; c0 < NIN; c0 += 32) {
        {
            int c4 = (tid & 7) * 4;
            int dr = tid >> 3;
            #pragma unroll
            for (int r = 0; r < 4; r++) {
                int d = dr + 32 * r;
                float4 w = *(const float4*)&W[(size_t)d * NIN + c0 + c4];
                *(float4*)&Wc[d * 36 + c4] = w;
            }
        }
        {
            int q4 = (tid & 15) * 4;
            int ccr = tid >> 4;
            #pragma unroll
            for (int r = 0; r < 2; r++) {
                int cc = ccr + 16 * r;
                float4 v = *(const float4*)&zb[(size_t)(c0 + cc) * Nn + n0 + q4];
                *(float4*)&zc[cc * 68 + q4] = v;
            }
        }
        __syncthreads();
        #pragma unroll 2
        for (int cc = 0; cc < 32; cc += 4) {
            float4 w4[8], z4[4];
            #pragma unroll
            for (int i = 0; i < 8; i++) w4[i] = *(const float4*)&Wc[(dA + i) * 36 + cc];
            #pragma unroll
            for (int u = 0; u < 4; u++) z4[u] = *(const float4*)&zc[(cc + u) * 68 + nA];
            #pragma unroll
            for (int i = 0; i < 8; i++) {
                float4 w = w4[i];
                acc[i][0] = fmaf(w.x, z4[0].x, fmaf(w.y, z4[1].x, fmaf(w.z, z4[2].x, fmaf(w.w, z4[3].x, acc[i][0]))));
                acc[i][1] = fmaf(w.x, z4[0].y, fmaf(w.y, z4[1].y, fmaf(w.z, z4[2].y, fmaf(w.w, z4[3].y, acc[i][1]))));
                acc[i][2] = fmaf(w.x, z4[0].z, fmaf(w.y, z4[1].z, fmaf(w.z, z4[2].z, fmaf(w.w, z4[3].z, acc[i][2]))));
                acc[i][3] = fmaf(w.x, z4[0].w, fmaf(w.y, z4[1].w, fmaf(w.z, z4[2].w, fmaf(w.w, z4[3].w, acc[i][3]))));
            }
        }
        __syncthreads();
    }
    #pragma unroll
    for (int j = 0; j < 4; j++) {
        int n = nA + j;
        float4 v0 = make_float4(acc[0][j], acc[1][j], acc[2][j], acc[3][j]);
        float4 v1 = make_float4(acc[4][j], acc[5][j], acc[6][j], acc[7][j]);
        *(float4*)&ze_s[n * ZSS + dA]     = v0;
        *(float4*)&ze_s[n * ZSS + dA + 4] = v1;
    }
    __syncthreads();

    if (tid < NT) {
        const float* row = &ze_s[tid * ZSS];
        float s = 0.f;
        #pragma unroll 8
        for (int d = 0; d < Dd; d += 4) {
            float4 v = *(const float4*)&row[d];
            s += v.x * v.x + v.y * v.y + v.z * v.z + v.w * v.w;
        }
        g_zsq[T0 + tid]  = s;
        g_zsrt[T0 + tid] = sqrtf(s);
    }

    for (int i = tid; i < NT * Dd; i += 256) {
        int tl = i >> 7;
        int d  = i & 127;
        float e = ze_s[tl * ZSS + d];
        __nv_bfloat16 b0 = __float2bfloat16_rn(e);
        float r1 = e - __bfloat162float(b0);
        __nv_bfloat16 b1 = __float2bfloat16_rn(r1);
        float r2 = r1 - __bfloat162float(b1);
        __nv_bfloat16 b2 = __float2bfloat16_rn(r2);
        size_t gi = (size_t)(T0 + tl) * PRS + d;
        g_a0[gi] = b0; g_a1[gi] = b1; g_a2[gi] = b2;
    }
}

// ---------------------------------------------------------------------------
// K3: mma.sync bf16x3 distance GEMM, TMA-bulk staged, + argmin/gather/scatter
// ---------------------------------------------------------------------------
__global__ void __launch_bounds__(256, 1)
vq_dist_kernel(const float* __restrict__ emb, float* __restrict__ out)
{
    extern __shared__ char smem_c[];
    const uint32_t sb = smem_u32(smem_c);
    const int tid  = threadIdx.x;
    const int lane = tid & 31;
    const int w    = tid >> 5;           // 8 warps
    const int wt0  = w * 16;             // warp token base (CTA-local)
    const int T0   = blockIdx.x * TPC;

    float* s_qsq  = (float*)(smem_c + OFF_QSQ);
    float* s_qsrt = (float*)(smem_c + OFF_QSRT);
    int*   s_cnt  = (int*)(smem_c + OFF_CNT);
    int*   s_ind  = (int*)(smem_c + OFF_IND);
    const uint32_t mb_a  = sb + OFF_MBAR;
    const uint32_t mb_b0 = sb + OFF_MBAR + 8;
    const uint32_t mb_b1 = sb + OFF_MBAR + 16;

    // ---- init barriers and launch A + first two B chunks via bulk TMA ----
    if (tid == 0) {
        MBARRIER_INIT(mb_a, 1);
        MBARRIER_INIT(mb_b0, 1);
        MBARRIER_INIT(mb_b1, 1);
        FENCE_PROXY_ASYNC();
        MBARRIER_EXPECT_TX(mb_a, 3 * AB);
        BULK_G2S(sb + OFF_A,          (const char*)g_a0 + (size_t)T0 * ARS_B, AB, mb_a);
        BULK_G2S(sb + OFF_A + AB,     (const char*)g_a1 + (size_t)T0 * ARS_B, AB, mb_a);
        BULK_G2S(sb + OFF_A + 2 * AB, (const char*)g_a2 + (size_t)T0 * ARS_B, AB, mb_a);
        MBARRIER_EXPECT_TX(mb_b0, 3 * BB);
        BULK_G2S(sb + OFF_B,          (const char*)g_e0, BB, mb_b0);
        BULK_G2S(sb + OFF_B + BB,     (const char*)g_e1, BB, mb_b0);
        BULK_G2S(sb + OFF_B + 2 * BB, (const char*)g_e2, BB, mb_b0);
        MBARRIER_EXPECT_TX(mb_b1, 3 * BB);
        BULK_G2S(sb + OFF_B + 3 * BB, (const char*)g_e0 + BB, BB, mb_b1);
        BULK_G2S(sb + OFF_B + 4 * BB, (const char*)g_e1 + BB, BB, mb_b1);
        BULK_G2S(sb + OFF_B + 5 * BB, (const char*)g_e2 + BB, BB, mb_b1);
    }

    // norms + counters via regular loads (one-time)
    for (int i = tid; i < Kk; i += 256) {
        s_cnt[i]  = 0;
        s_qsq[i]  = g_qsq[i];
        s_qsrt[i] = g_qsrt[i];
    }
    const float zsq0 = g_zsq[T0 + wt0 + (lane >> 2)];
    const float zsr0 = g_zsrt[T0 + wt0 + (lane >> 2)];
    const float zsq1 = g_zsq[T0 + wt0 + (lane >> 2) + 8];
    const float zsr1 = g_zsrt[T0 + wt0 + (lane >> 2) + 8];
    __syncthreads();   // barriers initialized + norms staged

    // ldmatrix addresses
    uint32_t a_addr[3];
    {
        uint32_t arow = wt0 + (lane & 15);
        uint32_t acol = ((lane >> 4) << 3);
        #pragma unroll
        for (int s = 0; s < 3; s++)
            a_addr[s] = sb + OFF_A + s * AB + arow * ARS_B + acol * 2;
    }
    // B x4: lanes 0-7 rows 0-7 col0 | 8-15 rows 0-7 col16B | 16-23 rows 8-15 col0 | 24-31 rows 8-15 col16B
    const uint32_t b_lane_off =
        (uint32_t)(((lane & 7) + ((lane >> 4) << 3)) * ARS_B + (((lane >> 3) & 1) << 4));
    const uint32_t b_base0 = sb + OFF_B + b_lane_off;

    float bd2_0 = __int_as_float(0x7f800000), bdn_0 = 1.f;
    float bd2_1 = __int_as_float(0x7f800000), bdn_1 = 1.f;
    int   bid_0 = 0, bid_1 = 0;

    MBARRIER_WAIT_PARITY(mb_a, 0);

    for (int cc = 0; cc < NCH; cc++) {
        MBARRIER_WAIT_PARITY((cc & 1) ? mb_b1 : mb_b0, (cc >> 1) & 1);

        float acc[8][4];
        #pragma unroll
        for (int nt = 0; nt < 8; nt++)
            #pragma unroll
            for (int q = 0; q < 4; q++) acc[nt][q] = 0.f;

        const uint32_t bbuf = b_base0 + (uint32_t)((cc & 1) * (3 * BB));

        #pragma unroll 2
        for (int ks = 0; ks < 8; ks++) {
            uint32_t a0f[4], a1f[4], a2f[4];
            ldsm_x4(a0f, a_addr[0] + ks * 32);
            ldsm_x4(a1f, a_addr[1] + ks * 32);
            ldsm_x4(a2f, a_addr[2] + ks * 32);
            #pragma unroll
            for (int ntp = 0; ntp < 4; ntp++) {
                uint32_t b0f[4], b1f[4], b2f[4];
                uint32_t bt = bbuf + (uint32_t)(ntp * 16 * ARS_B + ks * 32);
                ldsm_x4(b0f, bt);
                ldsm_x4(b1f, bt + BB);
                ldsm_x4(b2f, bt + 2 * BB);
                // nt even = rows 0-7 of pair -> {b[0],b[1]}; nt odd -> {b[2],b[3]}
                mma_bf16(acc[2 * ntp],     a0f, b0f);
                mma_bf16(acc[2 * ntp],     a1f, b0f);
                mma_bf16(acc[2 * ntp],     a0f, b1f);
                mma_bf16(acc[2 * ntp],     a1f, b1f);
                mma_bf16(acc[2 * ntp],     a2f, b0f);
                mma_bf16(acc[2 * ntp],     a0f, b2f);
                mma_bf16(acc[2 * ntp + 1], a0f, b0f + 2);
                mma_bf16(acc[2 * ntp + 1], a1f, b0f + 2);
                mma_bf16(acc[2 * ntp + 1], a0f, b1f + 2);
                mma_bf16(acc[2 * ntp + 1], a1f, b1f + 2);
                mma_bf16(acc[2 * ntp + 1], a2f, b0f + 2);
                mma_bf16(acc[2 * ntp + 1], a0f, b2f + 2);
            }
        }

        // fold chunk dots into running argmin
        #pragma unroll
        for (int nt = 0; nt < 8; nt++) {
            int cb = cc * KCH + nt * 8 + ((lane & 3) << 1);
            #pragma unroll
            for (int ci = 0; ci < 2; ci++) {
                int k = cb + ci;
                float qs = s_qsq[k];
                float qr = s_qsrt[k];
                {
                    float d2 = fmaxf(fmaf(-2.f, acc[nt][ci], zsq0 + qs), 0.f);
                    float den = zsr0 + qr, dn2 = den * den;
                    float lhs = d2 * bdn_0, rhs = bd2_0 * dn2;
                    if (lhs < rhs) { bd2_0 = d2; bdn_0 = dn2; bid_0 = k; }
                }
                {
                    float d2 = fmaxf(fmaf(-2.f, acc[nt][2 + ci], zsq1 + qs), 0.f);
                    float den = zsr1 + qr, dn2 = den * den;
                    float lhs = d2 * bdn_1, rhs = bd2_1 * dn2;
                    if (lhs < rhs) { bd2_1 = d2; bdn_1 = dn2; bid_1 = k; }
                }
            }
        }
        __syncthreads();   // all warps done reading this buffer

        // prefetch chunk cc+2 into the buffer just freed
        if (tid == 0 && cc + 2 < NCH) {
            uint32_t mb = (cc & 1) ? mb_b1 : mb_b0;
            uint32_t dst = sb + OFF_B + (uint32_t)((cc & 1) * (3 * BB));
            size_t so = (size_t)(cc + 2) * BB;
            MBARRIER_EXPECT_TX(mb, 3 * BB);
            BULK_G2S(dst,          (const char*)g_e0 + so, BB, mb);
            BULK_G2S(dst + BB,     (const char*)g_e1 + so, BB, mb);
            BULK_G2S(dst + 2 * BB, (const char*)g_e2 + so, BB, mb);
        }
    }

    // reduce across the 4 lanes of each token quad
    #pragma unroll
    for (int off = 1; off < 4; off <<= 1) {
        float od2 = __shfl_xor_sync(0xffffffffu, bd2_0, off);
        float odn = __shfl_xor_sync(0xffffffffu, bdn_0, off);
        int   oid = __shfl_xor_sync(0xffffffffu, bid_0, off);
        float lhs = od2 * bdn_0, rhs = bd2_0 * odn;
        if (lhs < rhs || (lhs == rhs && oid < bid_0)) { bd2_0 = od2; bdn_0 = odn; bid_0 = oid; }
        od2 = __shfl_xor_sync(0xffffffffu, bd2_1, off);
        odn = __shfl_xor_sync(0xffffffffu, bdn_1, off);
        oid = __shfl_xor_sync(0xffffffffu, bid_1, off);
        lhs = od2 * bdn_1; rhs = bd2_1 * odn;
        if (lhs < rhs || (lhs == rhs && oid < bid_1)) { bd2_1 = od2; bdn_1 = odn; bid_1 = oid; }
    }
    if ((lane & 3) == 0) {
        s_ind[wt0 + (lane >> 2)]     = bid_0;
        s_ind[wt0 + (lane >> 2) + 8] = bid_1;
    }
    __syncthreads();

    if (tid < TPC) atomicAdd(&s_cnt[s_ind[tid]], 1);

    // ---- zq gather + EMA scatter : 2 threads per token ----
    {
        int tl   = tid >> 1;
        int half = tid & 1;
        int ci   = s_ind[tl];
        int token = T0 + tl;
        int b = token >> 12;
        int n = token & (Nn - 1);
        const float4* er = (const float4*)(emb + (size_t)ci * Dd + half * 64);
        float* op = out + (size_t)b * Dd * Nn + n + (size_t)(half * 64) * Nn;
        #pragma unroll 4
        for (int d4 = 0; d4 < 16; d4++) {
            float4 v = er[d4];
            op[(size_t)(d4 * 4 + 0) * Nn] = v.x;
            op[(size_t)(d4 * 4 + 1) * Nn] = v.y;
            op[(size_t)(d4 * 4 + 2) * Nn] = v.z;
            op[(size_t)(d4 * 4 + 3) * Nn] = v.w;
        }
        float* zs = g_zsum + (size_t)ci * Dd + half * 64;
        uint32_t arow = (uint32_t)(tl * ARS_B + half * 128);
        #pragma unroll 2
        for (int c8 = 0; c8 < 8; c8++) {
            uint4 v0 = *(const uint4*)(smem_c + OFF_A + arow + c8 * 16);
            uint4 v1 = *(const uint4*)(smem_c + OFF_A + AB + arow + c8 * 16);
            uint4 v2 = *(const uint4*)(smem_c + OFF_A + 2 * AB + arow + c8 * 16);
            const __nv_bfloat16* p0 = (const __nv_bfloat16*)&v0;
            const __nv_bfloat16* p1 = (const __nv_bfloat16*)&v1;
            const __nv_bfloat16* p2 = (const __nv_bfloat16*)&v2;
            #pragma unroll
            for (int e = 0; e < 8; e++) {
                float ze = __bfloat162float(p0[e]) + __bfloat162float(p1[e]) + __bfloat162float(p2[e]);
                atomicAdd(&zs[c8 * 8 + e], ze);
            }
        }
    }
    __syncthreads();
    for (int i = tid; i < Kk; i += 256) {
        int c = s_cnt[i];
        if (c) atomicAdd(&g_nsum[i], (float)c);
    }
}

// ---------------------------------------------------------------------------
// K4: finalize EMA outputs
// ---------------------------------------------------------------------------
__global__ void vq_ema_kernel(const float* __restrict__ numer,
                              const float* __restrict__ denom,
                              float* __restrict__ out)
{
    int i = blockIdx.x * blockDim.x + threadIdx.x;
    out[NUM_OFF + i] = 0.99f * numer[i] + 0.01f * g_zsum[i];
    if (i < Kk)
        out[DEN_OFF + i] = 0.99f * denom[i] + 0.01f * g_nsum[i];
}

// ---------------------------------------------------------------------------
extern "C" void kernel_launch(void* const* d_in, const int* in_sizes, int n_in,
                              void* d_out, int out_size)
{
    const float* z     = (const float*)d_in[0];
    const float* W     = (const float*)d_in[1];
    const float* emb   = (const float*)d_in[2];
    const float* numer = (const float*)d_in[3];
    const float* denom = (const float*)d_in[4];
    float* out = (float*)d_out;

    const int ze_smem = (NT * ZSS + 128 * 36 + 32 * 68) * 4;  // 60928 B
    cudaFuncSetAttribute(vq_ze_kernel,
                         cudaFuncAttributeMaxDynamicSharedMemorySize, ze_smem);
    cudaFuncSetAttribute(vq_dist_kernel,
                         cudaFuncAttributeMaxDynamicSharedMemorySize, SM_TOTAL);

    vq_prep_kernel<<<Kk, Dd>>>(emb);
    dim3 gz(Nn / NT, Bb);
    vq_ze_kernel<<<gz, 256, ze_smem>>>(z, W);
    vq_dist_kernel<<<TOK / TPC, 256, SM_TOTAL>>>(emb, out);
    vq_ema_kernel<<<(Kk * Dd) / 256, 256>>>(numer, denom, out);
}